// round 7
// baseline (speedup 1.0000x reference)
#include <cuda_runtime.h>
#include <cuda_fp16.h>

// Fused curve-LUT apply (trilinear grid_sample over 8x256x256 control grid + tanh).
//
// R7: vectorized shared reads. Layout: per control point, per z-level, one
// 16-byte chunk {pair_c0, pair_c1, pair_c2, pad} where pair_c[z] =
// (v[z], v[z+1]) in fp16 (overlap; z=7 -> (v7,v7)).  A corner read is ONE
// LDS.128 giving all 3 channels' z-lerp endpoints: 12 LDS.128/px vs 36
// LDS.32/px.  Corner blend: pairwise HMUL2/HFMA2, HADD2 combine, single
// half2->float2 convert, fp32 z-lerp.  Point stride = 9 chunks (odd in the
// 8 chunk-slot bank space).  smem 43.2KB static, 512 thr, 4 CTAs/SM.

#define TW 32
#define TH 32
#define XS 10
#define YS 10
#define NP (XS * YS)          // 100 points
#define PCH 9                 // 16B chunks per point (8 z + 1 pad)
#define PSTRB (PCH * 16)      // 144 bytes per point
#define ISTRB (NP * PSTRB)    // bytes per curve set i
#define NTHREADS 512

__device__ __forceinline__ float fast_tanh(float v) {
    float y;
    asm("tanh.approx.f32 %0, %1;" : "=f"(y) : "f"(v));
    return y;
}

__global__ __launch_bounds__(NTHREADS, 4)
void curve_apply_kernel(const float* __restrict__ x,
                        const float* __restrict__ param,
                        float* __restrict__ out)
{
    __shared__ __align__(16) __half sh[3 * NP * PCH * 8];   // 43,200 B

    const int b  = blockIdx.z;
    const int w0 = blockIdx.x * TW;
    const int h0 = blockIdx.y * TH;
    const float r = 255.0f / 1023.0f;
    const int xbase = (int)floorf((float)w0 * r);
    const int ybase = (int)floorf((float)h0 * r);
    const int tid = threadIdx.x;

    // ---- Stage control patch ----
    // plane = c*24 + i*8 + z.  Half index within point: z*8 + 2c (+1 for .y).
    // v[z] -> chunk z slot (pair.x) and chunk z-1 slot (pair.y); z==7 also its own .y.
    const float* prm = param + (size_t)b * 72 * 65536;
    #pragma unroll 1
    for (int idx = tid; idx < 72 * NP; idx += NTHREADS) {
        int plane = idx / NP;
        int pos   = idx - plane * NP;
        int dy = pos / XS;
        int dx = pos - dy * XS;
        int yy = min(ybase + dy, 255);
        int xx = min(xbase + dx, 255);
        float v = __ldg(prm + plane * 65536 + yy * 256 + xx);
        int c  = plane / 24;
        int rm = plane - c * 24;
        int i  = rm >> 3;
        int z  = rm & 7;
        __half hv = __float2half_rn(v);
        __half* hb = sh + (i * NP + pos) * (PCH * 8) + 2 * c;
        hb[z * 8] = hv;                       // chunk z, pair.x
        if (z > 0)  hb[(z - 1) * 8 + 1] = hv; // chunk z-1, pair.y
        if (z == 7) hb[7 * 8 + 1] = hv;       // chunk 7, pair.y (depth clamp)
    }
    __syncthreads();

    // ---- Pixel loop: 16 warps, lane = x, 2 rows per thread ----
    const int lane = tid & 31;
    const int rowi = tid >> 5;
    const int w = w0 + lane;

    float ixf = fminf((float)w * r, 255.0f);
    float x0f = floorf(ixf);
    float wx  = ixf - x0f;
    int   x0  = (int)x0f;
    int   dx0 = x0 - xbase;
    int   dx1 = min(x0 + 1, 255) - xbase;

    const float* xb = x   + (size_t)b * 3 * 1048576;
    float*       ob = out + (size_t)b * 3 * 1048576;

    const int h_a = h0 + rowi;
    const int h_b = h_a + 16;
    const int pixA = h_a * 1024 + w;
    const int pixB = h_b * 1024 + w;

    float gz_[2][3];
    gz_[0][0] = __ldg(xb + pixA);
    gz_[0][1] = __ldg(xb + 1048576 + pixA);
    gz_[0][2] = __ldg(xb + 2097152 + pixA);
    gz_[1][0] = __ldg(xb + pixB);
    gz_[1][1] = __ldg(xb + 1048576 + pixB);
    gz_[1][2] = __ldg(xb + 2097152 + pixB);

    const char* shc = (const char*)sh;

    #pragma unroll
    for (int k = 0; k < 2; k++) {
        const int h   = (k == 0) ? h_a : h_b;
        const int pix = (k == 0) ? pixA : pixB;

        float iyf = fminf((float)h * r, 255.0f);
        float y0f = floorf(iyf);
        float wy  = iyf - y0f;
        int   y0  = (int)y0f;
        int   dy0 = y0 - ybase;
        int   dy1 = min(y0 + 1, 255) - ybase;

        // corner byte offsets (within one curve set)
        int cb00 = (dy0 * XS + dx0) * PSTRB;
        int cb01 = (dy0 * XS + dx1) * PSTRB;
        int cb10 = (dy1 * XS + dx0) * PSTRB;
        int cb11 = (dy1 * XS + dx1) * PSTRB;

        float w11 = wy * wx;
        float w10 = wy - w11;
        float w01 = wx - w11;
        float w00 = 1.0f - wy - wx + w11;

        const __half2 hw00 = __half2half2(__float2half_rn(w00));
        const __half2 hw01 = __half2half2(__float2half_rn(w01));
        const __half2 hw10 = __half2half2(__float2half_rn(w10));
        const __half2 hw11 = __half2half2(__float2half_rn(w11));

        float acc0 = 0.f, acc1 = 0.f, acc2 = 0.f;

        #pragma unroll
        for (int i = 0; i < 3; i++) {
            float gz  = gz_[k][i];
            float izf = fminf(fmaxf(fmaf(gz, 3.5f, 3.5f), 0.0f), 7.0f);
            float z0f = floorf(izf);
            float wz  = izf - z0f;
            int   zo  = (int)z0f * 16;                 // chunk byte offset
            const char* base = shc + i * ISTRB + zo;

            uint4 q00 = *(const uint4*)(base + cb00);
            uint4 q01 = *(const uint4*)(base + cb01);
            __half2 t0 = __hfma2(hw01, *(__half2*)&q01.x, __hmul2(hw00, *(__half2*)&q00.x));
            __half2 t1 = __hfma2(hw01, *(__half2*)&q01.y, __hmul2(hw00, *(__half2*)&q00.y));
            __half2 t2 = __hfma2(hw01, *(__half2*)&q01.z, __hmul2(hw00, *(__half2*)&q00.z));

            uint4 q10 = *(const uint4*)(base + cb10);
            uint4 q11 = *(const uint4*)(base + cb11);
            t0 = __hadd2(t0, __hfma2(hw11, *(__half2*)&q11.x, __hmul2(hw10, *(__half2*)&q10.x)));
            t1 = __hadd2(t1, __hfma2(hw11, *(__half2*)&q11.y, __hmul2(hw10, *(__half2*)&q10.y)));
            t2 = __hadd2(t2, __hfma2(hw11, *(__half2*)&q11.z, __hmul2(hw10, *(__half2*)&q10.z)));

            float2 f0 = __half22float2(t0);
            float2 f1 = __half22float2(t1);
            float2 f2 = __half22float2(t2);
            acc0 += fmaf(wz, f0.y - f0.x, f0.x);
            acc1 += fmaf(wz, f1.y - f1.x, f1.x);
            acc2 += fmaf(wz, f2.y - f2.x, f2.x);
        }

        ob[pix]           = fast_tanh(acc0);
        ob[1048576 + pix] = fast_tanh(acc1);
        ob[2097152 + pix] = fast_tanh(acc2);
    }
}

extern "C" void kernel_launch(void* const* d_in, const int* in_sizes, int n_in,
                              void* d_out, int out_size)
{
    const float* x     = (const float*)d_in[0];   // [4,3,1024,1024] fp32
    const float* param = (const float*)d_in[1];   // [4,72,256,256]  fp32
    float*       out   = (float*)d_out;           // [4,3,1024,1024] fp32

    dim3 grid(1024 / TW, 1024 / TH, 4);
    curve_apply_kernel<<<grid, NTHREADS>>>(x, param, out);
}